// round 2
// baseline (speedup 1.0000x reference)
#include <cuda_runtime.h>

#define N_NODES 100000
#define KDIM 128

// ---------------- scratch (device globals; no allocation allowed) ----------
__device__ float4 g_XL[N_NODES * 32];   // x @ Wl0 (layer0), later reused as H
__device__ float4 g_XR[N_NODES * 32];   // x @ Wr0
__device__ float4 g_AGG0[N_NODES * 32]; // scatter accumulator layer0
__device__ float4 g_HL[N_NODES * 16];   // h @ Wl1
__device__ float4 g_AGG1[N_NODES * 16]; // scatter accumulator layer1
__device__ int    g_cnt[N_NODES];       // in-degree

// ---------------- vectorized global reduction (sm_90+) ---------------------
__device__ __forceinline__ void red_add_v4(float4* addr, float4 v) {
    asm volatile("red.global.add.v4.f32 [%0], {%1, %2, %3, %4};"
                 :: "l"(addr), "f"(v.x), "f"(v.y), "f"(v.z), "f"(v.w)
                 : "memory");
}

// ---------------- zero accumulators + counters ------------------------------
__global__ void k_zero() {
    int t = blockIdx.x * blockDim.x + threadIdx.x;
    if (t < N_NODES * 32) g_AGG0[t] = make_float4(0.f, 0.f, 0.f, 0.f);
    if (t < N_NODES * 16) g_AGG1[t] = make_float4(0.f, 0.f, 0.f, 0.f);
    if (t < N_NODES)      g_cnt[t] = 0;
}

// ---------------- in-degree count -------------------------------------------
__global__ void k_count(const int* __restrict__ dst, int E) {
    int t = blockIdx.x * blockDim.x + threadIdx.x;
    if (t < E) atomicAdd(&g_cnt[dst[t]], 1);
}

// ---------------- tiled SGEMM: C[M,BN] = A[M,128] @ W[128,BN] ---------------
// BM=128, BK=16, TM=8; 256 threads; BN is the full output width (grid over M only)
template<int BN, int TN>
__global__ void __launch_bounds__(256)
k_gemm(const float* __restrict__ A, const float* __restrict__ W,
       float* __restrict__ C, int M)
{
    constexpr int BM = 128, BK = 16, TM = 8;
    constexpr int TX = BN / TN;            // 16 for both configs

    __shared__ float As[BK][BM + 4];       // transposed A tile (pad 4)
    __shared__ float Bs[BK][BN];

    const int tid = threadIdx.x;
    const int tx = tid % TX;
    const int ty = tid / TX;
    const int r0 = blockIdx.x * BM;

    float acc[TM][TN];
#pragma unroll
    for (int i = 0; i < TM; i++)
#pragma unroll
        for (int j = 0; j < TN; j++) acc[i][j] = 0.f;

    for (int kt = 0; kt < KDIM; kt += BK) {
        // load A tile (BM x BK = 2048 floats = 512 float4; 2 per thread)
#pragma unroll
        for (int j = 0; j < 2; j++) {
            int v   = tid + j * 256;       // 0..511
            int row = v >> 2;
            int c4  = v & 3;
            float4 val = make_float4(0.f, 0.f, 0.f, 0.f);
            int gr = r0 + row;
            if (gr < M)
                val = *(const float4*)(A + (long)gr * KDIM + kt + c4 * 4);
            As[c4 * 4 + 0][row] = val.x;
            As[c4 * 4 + 1][row] = val.y;
            As[c4 * 4 + 2][row] = val.z;
            As[c4 * 4 + 3][row] = val.w;
        }
        // load W tile (BK x BN floats)
        constexpr int WV = (BK * BN / 4) / 256;   // 2 for BN=128, 1 for BN=64
#pragma unroll
        for (int j = 0; j < WV; j++) {
            int v  = tid + j * 256;
            int kr = v / (BN / 4);
            int c4 = v % (BN / 4);
            *(float4*)&Bs[kr][c4 * 4] =
                *(const float4*)(W + (long)(kt + kr) * BN + c4 * 4);
        }
        __syncthreads();

#pragma unroll
        for (int kk = 0; kk < BK; kk++) {
            float a[TM], b[TN];
#pragma unroll
            for (int i = 0; i < TM; i += 4)
                *(float4*)&a[i] = *(float4*)&As[kk][ty * TM + i];
#pragma unroll
            for (int j = 0; j < TN; j += 4)
                *(float4*)&b[j] = *(float4*)&Bs[kk][tx * TN + j];
#pragma unroll
            for (int i = 0; i < TM; i++)
#pragma unroll
                for (int j = 0; j < TN; j++)
                    acc[i][j] += a[i] * b[j];
        }
        __syncthreads();
    }

#pragma unroll
    for (int i = 0; i < TM; i++) {
        int gr = r0 + ty * TM + i;
        if (gr < M) {
#pragma unroll
            for (int j = 0; j < TN; j += 4)
                *(float4*)(C + (long)gr * BN + tx * TN + j) = *(float4*)&acc[i][j];
        }
    }
}

// ---------------- edge scatter, 128-dim (layer 0) ---------------------------
__global__ void k_scatter128(const int* __restrict__ src,
                             const int* __restrict__ dst, int E) {
    int t = blockIdx.x * blockDim.x + threadIdx.x;
    if (t >= E * 32) return;
    int e = t >> 5, c = t & 31;
    int s = __ldg(&src[e]);
    int d = __ldg(&dst[e]);
    float4 v = g_XL[s * 32 + c];
    red_add_v4(&g_AGG0[d * 32 + c], v);
}

// ---------------- edge scatter, 64-dim (layer 1) ----------------------------
__global__ void k_scatter64(const int* __restrict__ src,
                            const int* __restrict__ dst, int E) {
    int t = blockIdx.x * blockDim.x + threadIdx.x;
    if (t >= E * 16) return;
    int e = t >> 4, c = t & 15;
    int s = __ldg(&src[e]);
    int d = __ldg(&dst[e]);
    float4 v = g_HL[s * 16 + c];
    red_add_v4(&g_AGG1[d * 16 + c], v);
}

// ---------------- h = relu(AGG0/cnt + bl0 + XR), store into g_XL ------------
__global__ void k_combine0(const float* __restrict__ bl0) {
    int t = blockIdx.x * blockDim.x + threadIdx.x;
    if (t >= N_NODES * 32) return;
    int row = t >> 5, c = t & 31;
    float inv = 1.f / fmaxf((float)g_cnt[row], 1.f);
    float4 a = g_AGG0[t];
    float4 x = g_XR[t];
    float4 b = ((const float4*)bl0)[c];
    float4 r;
    r.x = fmaxf(fmaf(a.x, inv, b.x) + x.x, 0.f);
    r.y = fmaxf(fmaf(a.y, inv, b.y) + x.y, 0.f);
    r.z = fmaxf(fmaf(a.z, inv, b.z) + x.z, 0.f);
    r.w = fmaxf(fmaf(a.w, inv, b.w) + x.w, 0.f);
    g_XL[t] = r;
}

// ---------------- out += AGG1/cnt + bl1 (out already holds h@Wr1) -----------
__global__ void k_final(const float* __restrict__ bl1, float4* __restrict__ out) {
    int t = blockIdx.x * blockDim.x + threadIdx.x;
    if (t >= N_NODES * 16) return;
    int row = t >> 4, c = t & 15;
    float inv = 1.f / fmaxf((float)g_cnt[row], 1.f);
    float4 a = g_AGG1[t];
    float4 o = out[t];
    float4 b = ((const float4*)bl1)[c];
    o.x += fmaf(a.x, inv, b.x);
    o.y += fmaf(a.y, inv, b.y);
    o.z += fmaf(a.z, inv, b.z);
    o.w += fmaf(a.w, inv, b.w);
    out[t] = o;
}

// ---------------- launch -----------------------------------------------------
extern "C" void kernel_launch(void* const* d_in, const int* in_sizes, int n_in,
                              void* d_out, int out_size) {
    const float* x   = (const float*)d_in[0];
    const int*   ei  = (const int*)d_in[1];    // JAX downcasts int64->int32 (x64 disabled)
    const float* Wl0 = (const float*)d_in[2];
    const float* bl0 = (const float*)d_in[3];
    const float* Wr0 = (const float*)d_in[4];
    const float* Wl1 = (const float*)d_in[5];
    const float* bl1 = (const float*)d_in[6];
    const float* Wr1 = (const float*)d_in[7];

    const int E = in_sizes[1] / 2;
    const int* src = ei;
    const int* dst = ei + E;
    const int M = N_NODES;

    float *pXL, *pXR, *pHL;
    cudaGetSymbolAddress((void**)&pXL, g_XL);
    cudaGetSymbolAddress((void**)&pXR, g_XR);
    cudaGetSymbolAddress((void**)&pHL, g_HL);

    k_zero<<<(N_NODES * 32 + 255) / 256, 256>>>();
    k_count<<<(E + 255) / 256, 256>>>(dst, E);

    // layer 0: transform, aggregate, combine
    k_gemm<128, 8><<<(M + 127) / 128, 256>>>(x, Wl0, pXL, M);
    k_gemm<128, 8><<<(M + 127) / 128, 256>>>(x, Wr0, pXR, M);
    k_scatter128<<<(E * 32 + 255) / 256, 256>>>(src, dst, E);
    k_combine0<<<(M * 32 + 255) / 256, 256>>>(bl0);

    // layer 1: transform (HR straight into d_out), aggregate, combine
    k_gemm<64, 4><<<(M + 127) / 128, 256>>>((const float*)pXL, Wl1, pHL, M);
    k_gemm<64, 4><<<(M + 127) / 128, 256>>>((const float*)pXL, Wr1, (float*)d_out, M);
    k_scatter64<<<(E * 16 + 255) / 256, 256>>>(src, dst, E);
    k_final<<<(M * 16 + 255) / 256, 256>>>(bl1, (float4*)d_out);
}

// round 5
// speedup vs baseline: 1.0062x; 1.0062x over previous
#include <cuda_runtime.h>

#define N_NODES 100000
#define KDIM 128

typedef unsigned long long u64;

// ---------------- scratch (device globals; no allocation allowed) ----------
__device__ float4 g_XL[N_NODES * 32];   // x @ Wl0 (layer0), later reused as H
__device__ float4 g_XR[N_NODES * 32];   // x @ Wr0
__device__ float4 g_AGG0[N_NODES * 32]; // scatter accumulator layer0
__device__ float4 g_HL[N_NODES * 16];   // h @ Wl1
__device__ float4 g_AGG1[N_NODES * 16]; // scatter accumulator layer1
__device__ int    g_cnt[N_NODES];       // in-degree

// ---------------- packed fp32x2 helpers (Blackwell FFMA2) -------------------
__device__ __forceinline__ u64 dup2(float a) {
    u64 r; asm("mov.b64 %0, {%1, %1};" : "=l"(r) : "f"(a)); return r;
}
__device__ __forceinline__ void ffma2(u64 &acc, u64 a, u64 b) {
    asm("fma.rn.f32x2 %0, %1, %2, %0;" : "+l"(acc) : "l"(a), "l"(b));
}
__device__ __forceinline__ float2 unpack2(u64 v) {
    float2 r; asm("mov.b64 {%0, %1}, %2;" : "=f"(r.x), "=f"(r.y) : "l"(v));
    return r;
}

// ---------------- vectorized global reduction (sm_90+) ---------------------
__device__ __forceinline__ void red_add_v4(float4* addr, float4 v) {
    asm volatile("red.global.add.v4.f32 [%0], {%1, %2, %3, %4};"
                 :: "l"(addr), "f"(v.x), "f"(v.y), "f"(v.z), "f"(v.w)
                 : "memory");
}

// ---------------- zero accumulators + counters ------------------------------
__global__ void k_zero() {
    int t = blockIdx.x * blockDim.x + threadIdx.x;
    if (t < N_NODES * 32) g_AGG0[t] = make_float4(0.f, 0.f, 0.f, 0.f);
    if (t < N_NODES * 16) g_AGG1[t] = make_float4(0.f, 0.f, 0.f, 0.f);
    if (t < N_NODES)      g_cnt[t] = 0;
}

// ---------------- in-degree count -------------------------------------------
__global__ void k_count(const int* __restrict__ dst, int E) {
    int t = blockIdx.x * blockDim.x + threadIdx.x;
    if (t < E) atomicAdd(&g_cnt[dst[t]], 1);
}

// ---------------- tiled SGEMM with packed FFMA2 -----------------------------
// C[M,BN] = A[M,128] @ W[128,BN]; BM=128, BK=16, TM=8; 256 threads.
template<int BN, int TN>
__global__ void __launch_bounds__(256)
k_gemm(const float* __restrict__ A, const float* __restrict__ W,
       float* __restrict__ C, int M)
{
    constexpr int BM = 128, BK = 16, TM = 8;
    constexpr int TX = BN / TN;            // 16 for both configs
    constexpr int TP = TN / 2;             // packed pairs per row

    __shared__ float As[BK][BM + 4];       // transposed A tile (pad 4)
    __shared__ float Bs[BK][BN];

    const int tid = threadIdx.x;
    const int tx = tid % TX;
    const int ty = tid / TX;
    const int r0 = blockIdx.x * BM;

    u64 acc[TM][TP];
#pragma unroll
    for (int i = 0; i < TM; i++)
#pragma unroll
        for (int j = 0; j < TP; j++) acc[i][j] = 0ULL;

    for (int kt = 0; kt < KDIM; kt += BK) {
        // load A tile (BM x BK = 2048 floats = 512 float4; 2 per thread)
#pragma unroll
        for (int j = 0; j < 2; j++) {
            int v   = tid + j * 256;       // 0..511
            int row = v >> 2;
            int c4  = v & 3;
            float4 val = make_float4(0.f, 0.f, 0.f, 0.f);
            int gr = r0 + row;
            if (gr < M)
                val = *(const float4*)(A + (long)gr * KDIM + kt + c4 * 4);
            As[c4 * 4 + 0][row] = val.x;
            As[c4 * 4 + 1][row] = val.y;
            As[c4 * 4 + 2][row] = val.z;
            As[c4 * 4 + 3][row] = val.w;
        }
        // load W tile (BK x BN floats)
        constexpr int WV = (BK * BN / 4) / 256;   // 2 for BN=128, 1 for BN=64
#pragma unroll
        for (int j = 0; j < WV; j++) {
            int v  = tid + j * 256;
            int kr = v / (BN / 4);
            int c4 = v % (BN / 4);
            *(float4*)&Bs[kr][c4 * 4] =
                *(const float4*)(W + (long)(kt + kr) * BN + c4 * 4);
        }
        __syncthreads();

#pragma unroll
        for (int kk = 0; kk < BK; kk++) {
            float a[TM];
#pragma unroll
            for (int i = 0; i < TM; i += 4)
                *(float4*)&a[i] = *(float4*)&As[kk][ty * TM + i];

            u64 b2[TP];                    // pair j covers columns 2j, 2j+1
#pragma unroll
            for (int j = 0; j < TP; j += 2) {
                ulonglong2 t = *(const ulonglong2*)&Bs[kk][tx * TN + 2 * j];
                b2[j]     = t.x;
                b2[j + 1] = t.y;
            }
#pragma unroll
            for (int i = 0; i < TM; i++) {
                u64 ad = dup2(a[i]);
#pragma unroll
                for (int j = 0; j < TP; j++)
                    ffma2(acc[i][j], ad, b2[j]);
            }
        }
        __syncthreads();
    }

#pragma unroll
    for (int i = 0; i < TM; i++) {
        int gr = r0 + ty * TM + i;
        if (gr < M) {
            float o[TN];
#pragma unroll
            for (int j = 0; j < TP; j++) {
                float2 p = unpack2(acc[i][j]);
                o[2 * j] = p.x; o[2 * j + 1] = p.y;
            }
#pragma unroll
            for (int j = 0; j < TN; j += 4)
                *(float4*)(C + (long)gr * BN + tx * TN + j) = *(float4*)&o[j];
        }
    }
}

// ---------------- edge scatter, 128-dim (layer 0) ---------------------------
__global__ void k_scatter128(const int* __restrict__ src,
                             const int* __restrict__ dst, int E) {
    int t = blockIdx.x * blockDim.x + threadIdx.x;
    if (t >= E * 32) return;
    int e = t >> 5, c = t & 31;
    int s = __ldg(&src[e]);
    int d = __ldg(&dst[e]);
    float4 v = g_XL[s * 32 + c];
    red_add_v4(&g_AGG0[d * 32 + c], v);
}

// ---------------- edge scatter, 64-dim (layer 1) ----------------------------
__global__ void k_scatter64(const int* __restrict__ src,
                            const int* __restrict__ dst, int E) {
    int t = blockIdx.x * blockDim.x + threadIdx.x;
    if (t >= E * 16) return;
    int e = t >> 4, c = t & 15;
    int s = __ldg(&src[e]);
    int d = __ldg(&dst[e]);
    float4 v = g_HL[s * 16 + c];
    red_add_v4(&g_AGG1[d * 16 + c], v);
}

// ---------------- h = relu(AGG0/cnt + bl0 + XR), store into g_XL ------------
__global__ void k_combine0(const float* __restrict__ bl0) {
    int t = blockIdx.x * blockDim.x + threadIdx.x;
    if (t >= N_NODES * 32) return;
    int row = t >> 5, c = t & 31;
    float inv = 1.f / fmaxf((float)g_cnt[row], 1.f);
    float4 a = g_AGG0[t];
    float4 x = g_XR[t];
    float4 b = ((const float4*)bl0)[c];
    float4 r;
    r.x = fmaxf(fmaf(a.x, inv, b.x) + x.x, 0.f);
    r.y = fmaxf(fmaf(a.y, inv, b.y) + x.y, 0.f);
    r.z = fmaxf(fmaf(a.z, inv, b.z) + x.z, 0.f);
    r.w = fmaxf(fmaf(a.w, inv, b.w) + x.w, 0.f);
    g_XL[t] = r;
}

// ---------------- out += AGG1/cnt + bl1 (out already holds h@Wr1) -----------
__global__ void k_final(const float* __restrict__ bl1, float4* __restrict__ out) {
    int t = blockIdx.x * blockDim.x + threadIdx.x;
    if (t >= N_NODES * 16) return;
    int row = t >> 4, c = t & 15;
    float inv = 1.f / fmaxf((float)g_cnt[row], 1.f);
    float4 a = g_AGG1[t];
    float4 o = out[t];
    float4 b = ((const float4*)bl1)[c];
    o.x += fmaf(a.x, inv, b.x);
    o.y += fmaf(a.y, inv, b.y);
    o.z += fmaf(a.z, inv, b.z);
    o.w += fmaf(a.w, inv, b.w);
    out[t] = o;
}

// ---------------- launch -----------------------------------------------------
extern "C" void kernel_launch(void* const* d_in, const int* in_sizes, int n_in,
                              void* d_out, int out_size) {
    const float* x   = (const float*)d_in[0];
    const int*   ei  = (const int*)d_in[1];    // JAX downcasts int64->int32
    const float* Wl0 = (const float*)d_in[2];
    const float* bl0 = (const float*)d_in[3];
    const float* Wr0 = (const float*)d_in[4];
    const float* Wl1 = (const float*)d_in[5];
    const float* bl1 = (const float*)d_in[6];
    const float* Wr1 = (const float*)d_in[7];

    const int E = in_sizes[1] / 2;
    const int* src = ei;
    const int* dst = ei + E;
    const int M = N_NODES;

    float *pXL, *pXR, *pHL;
    cudaGetSymbolAddress((void**)&pXL, g_XL);
    cudaGetSymbolAddress((void**)&pXR, g_XR);
    cudaGetSymbolAddress((void**)&pHL, g_HL);

    k_zero<<<(N_NODES * 32 + 255) / 256, 256>>>();
    k_count<<<(E + 255) / 256, 256>>>(dst, E);

    // layer 0: transform, aggregate, combine
    k_gemm<128, 8><<<(M + 127) / 128, 256>>>(x, Wl0, pXL, M);
    k_gemm<128, 8><<<(M + 127) / 128, 256>>>(x, Wr0, pXR, M);
    k_scatter128<<<(E * 32 + 255) / 256, 256>>>(src, dst, E);
    k_combine0<<<(M * 32 + 255) / 256, 256>>>(bl0);

    // layer 1: transform (HR straight into d_out), aggregate, combine
    k_gemm<64, 4><<<(M + 127) / 128, 256>>>((const float*)pXL, Wl1, pHL, M);
    k_gemm<64, 4><<<(M + 127) / 128, 256>>>((const float*)pXL, Wr1, (float*)d_out, M);
    k_scatter64<<<(E * 16 + 255) / 256, 256>>>(src, dst, E);
    k_final<<<(M * 16 + 255) / 256, 256>>>(bl1, (float4*)d_out);
}

// round 6
// speedup vs baseline: 1.1764x; 1.1691x over previous
#include <cuda_runtime.h>

#define N_NODES 100000
#define KDIM 128
#define MAX_E 1600000

// ---------------- scratch (device globals; no allocation allowed) ----------
__device__ float4 g_XL[N_NODES * 32];   // x @ Wl0
__device__ float4 g_XR[N_NODES * 32];   // x @ Wr0
__device__ float4 g_H [N_NODES * 32];   // hidden layer output
__device__ float4 g_HL[N_NODES * 16];   // h @ Wl1
__device__ int    g_cnt[N_NODES];       // in-degree
__device__ int    g_off[N_NODES];       // CSR row offsets
__device__ int    g_cur[N_NODES];       // fill cursors
__device__ int    g_eidx[MAX_E];        // CSR column (src) indices

// ---------------- zero counters ---------------------------------------------
__global__ void k_zero() {
    int t = blockIdx.x * blockDim.x + threadIdx.x;
    if (t < N_NODES) { g_cnt[t] = 0; g_cur[t] = 0; }
}

// ---------------- in-degree count -------------------------------------------
__global__ void k_count(const int* __restrict__ dst, int E) {
    int t = blockIdx.x * blockDim.x + threadIdx.x;
    if (t < E) atomicAdd(&g_cnt[dst[t]], 1);
}

// ---------------- single-block exclusive scan of g_cnt -> g_off -------------
__global__ void __launch_bounds__(1024) k_scan() {
    __shared__ int sm[1024];
    const int t = threadIdx.x;
    const int CH = (N_NODES + 1023) / 1024;
    const int s0 = t * CH;
    const int s1 = min(s0 + CH, N_NODES);
    int sum = 0;
    for (int i = s0; i < s1; i++) sum += g_cnt[i];
    sm[t] = sum;
    __syncthreads();
    int val = sum;
    for (int off = 1; off < 1024; off <<= 1) {
        int other = (t >= off) ? sm[t - off] : 0;
        __syncthreads();
        val += other;
        sm[t] = val;
        __syncthreads();
    }
    int run = val - sum;                  // exclusive prefix
    for (int i = s0; i < s1; i++) { g_off[i] = run; run += g_cnt[i]; }
}

// ---------------- CSR fill ---------------------------------------------------
__global__ void k_fill(const int* __restrict__ src, const int* __restrict__ dst,
                       int E) {
    int t = blockIdx.x * blockDim.x + threadIdx.x;
    if (t >= E) return;
    int d = dst[t];
    int p = atomicAdd(&g_cur[d], 1);
    g_eidx[g_off[d] + p] = src[t];
}

// ---------------- tiled SGEMM: C[M,BN] = A[M,128] @ W[128,BN] ---------------
template<int BN, int TN>
__global__ void __launch_bounds__(256)
k_gemm(const float* __restrict__ A, const float* __restrict__ W,
       float* __restrict__ C, int M)
{
    constexpr int BM = 128, BK = 16, TM = 8;
    constexpr int TX = BN / TN;

    __shared__ float As[BK][BM + 4];
    __shared__ float Bs[BK][BN];

    const int tid = threadIdx.x;
    const int tx = tid % TX;
    const int ty = tid / TX;
    const int r0 = blockIdx.x * BM;

    float acc[TM][TN];
#pragma unroll
    for (int i = 0; i < TM; i++)
#pragma unroll
        for (int j = 0; j < TN; j++) acc[i][j] = 0.f;

    for (int kt = 0; kt < KDIM; kt += BK) {
#pragma unroll
        for (int j = 0; j < 2; j++) {
            int v   = tid + j * 256;
            int row = v >> 2;
            int c4  = v & 3;
            float4 val = make_float4(0.f, 0.f, 0.f, 0.f);
            int gr = r0 + row;
            if (gr < M)
                val = *(const float4*)(A + (long)gr * KDIM + kt + c4 * 4);
            As[c4 * 4 + 0][row] = val.x;
            As[c4 * 4 + 1][row] = val.y;
            As[c4 * 4 + 2][row] = val.z;
            As[c4 * 4 + 3][row] = val.w;
        }
        constexpr int WV = (BK * BN / 4) / 256;
#pragma unroll
        for (int j = 0; j < WV; j++) {
            int v  = tid + j * 256;
            int kr = v / (BN / 4);
            int c4 = v % (BN / 4);
            *(float4*)&Bs[kr][c4 * 4] =
                *(const float4*)(W + (long)(kt + kr) * BN + c4 * 4);
        }
        __syncthreads();

#pragma unroll
        for (int kk = 0; kk < BK; kk++) {
            float a[TM], b[TN];
#pragma unroll
            for (int i = 0; i < TM; i += 4)
                *(float4*)&a[i] = *(float4*)&As[kk][ty * TM + i];
#pragma unroll
            for (int j = 0; j < TN; j += 4)
                *(float4*)&b[j] = *(float4*)&Bs[kk][tx * TN + j];
#pragma unroll
            for (int i = 0; i < TM; i++)
#pragma unroll
                for (int j = 0; j < TN; j++)
                    acc[i][j] += a[i] * b[j];
        }
        __syncthreads();
    }

#pragma unroll
    for (int i = 0; i < TM; i++) {
        int gr = r0 + ty * TM + i;
        if (gr < M) {
#pragma unroll
            for (int j = 0; j < TN; j += 4)
                *(float4*)(C + (long)gr * BN + tx * TN + j) = *(float4*)&acc[i][j];
        }
    }
}

// ---------------- layer-0 gather: H = relu(mean(XL[nbrs]) + bl0 + XR) -------
// one warp per node; lane c holds columns 4c..4c+3 (float4)
__global__ void __launch_bounds__(256)
k_gather128(const float* __restrict__ bl0) {
    int warp = (blockIdx.x * blockDim.x + threadIdx.x) >> 5;
    int lane = threadIdx.x & 31;
    if (warp >= N_NODES) return;
    int deg  = g_cnt[warp];
    int base = g_off[warp];

    float4 acc = make_float4(0.f, 0.f, 0.f, 0.f);
    for (int i0 = 0; i0 < deg; i0 += 32) {
        int my  = (i0 + lane < deg) ? g_eidx[base + i0 + lane] : 0;
        int lim = min(32, deg - i0);
#pragma unroll 4
        for (int j = 0; j < lim; j++) {
            int s = __shfl_sync(0xffffffffu, my, j);
            float4 v = g_XL[s * 32 + lane];
            acc.x += v.x; acc.y += v.y; acc.z += v.z; acc.w += v.w;
        }
    }
    float inv = 1.f / fmaxf((float)deg, 1.f);
    float4 b = ((const float4*)bl0)[lane];
    float4 x = g_XR[warp * 32 + lane];
    float4 r;
    r.x = fmaxf(fmaf(acc.x, inv, b.x) + x.x, 0.f);
    r.y = fmaxf(fmaf(acc.y, inv, b.y) + x.y, 0.f);
    r.z = fmaxf(fmaf(acc.z, inv, b.z) + x.z, 0.f);
    r.w = fmaxf(fmaf(acc.w, inv, b.w) + x.w, 0.f);
    g_H[warp * 32 + lane] = r;
}

// ---------------- layer-1 gather: out += mean(HL[nbrs]) + bl1 ---------------
// one warp per node; lane c holds columns 2c..2c+1 (float2); out holds h@Wr1
__global__ void __launch_bounds__(256)
k_gather64(const float* __restrict__ bl1, float* __restrict__ out) {
    int warp = (blockIdx.x * blockDim.x + threadIdx.x) >> 5;
    int lane = threadIdx.x & 31;
    if (warp >= N_NODES) return;
    int deg  = g_cnt[warp];
    int base = g_off[warp];

    const float2* H2 = (const float2*)g_HL;
    float2 acc = make_float2(0.f, 0.f);
    for (int i0 = 0; i0 < deg; i0 += 32) {
        int my  = (i0 + lane < deg) ? g_eidx[base + i0 + lane] : 0;
        int lim = min(32, deg - i0);
#pragma unroll 4
        for (int j = 0; j < lim; j++) {
            int s = __shfl_sync(0xffffffffu, my, j);
            float2 v = H2[s * 32 + lane];
            acc.x += v.x; acc.y += v.y;
        }
    }
    float inv = 1.f / fmaxf((float)deg, 1.f);
    float2 b = ((const float2*)bl1)[lane];
    float2* out2 = (float2*)out;
    float2 o = out2[warp * 32 + lane];
    o.x += fmaf(acc.x, inv, b.x);
    o.y += fmaf(acc.y, inv, b.y);
    out2[warp * 32 + lane] = o;
}

// ---------------- launch -----------------------------------------------------
extern "C" void kernel_launch(void* const* d_in, const int* in_sizes, int n_in,
                              void* d_out, int out_size) {
    const float* x   = (const float*)d_in[0];
    const int*   ei  = (const int*)d_in[1];    // int32 (JAX x64 disabled)
    const float* Wl0 = (const float*)d_in[2];
    const float* bl0 = (const float*)d_in[3];
    const float* Wr0 = (const float*)d_in[4];
    const float* Wl1 = (const float*)d_in[5];
    const float* bl1 = (const float*)d_in[6];
    const float* Wr1 = (const float*)d_in[7];

    const int E = in_sizes[1] / 2;
    const int* src = ei;
    const int* dst = ei + E;
    const int M = N_NODES;

    float *pXL, *pXR, *pH, *pHL;
    cudaGetSymbolAddress((void**)&pXL, g_XL);
    cudaGetSymbolAddress((void**)&pXR, g_XR);
    cudaGetSymbolAddress((void**)&pH,  g_H);
    cudaGetSymbolAddress((void**)&pHL, g_HL);

    // CSR build
    k_zero<<<(N_NODES + 255) / 256, 256>>>();
    k_count<<<(E + 255) / 256, 256>>>(dst, E);
    k_scan<<<1, 1024>>>();
    k_fill<<<(E + 255) / 256, 256>>>(src, dst, E);

    // layer 0: transform, gather+combine
    k_gemm<128, 8><<<(M + 127) / 128, 256>>>(x, Wl0, pXL, M);
    k_gemm<128, 8><<<(M + 127) / 128, 256>>>(x, Wr0, pXR, M);
    k_gather128<<<(N_NODES * 32 + 255) / 256, 256>>>(bl0);

    // layer 1: transform (root term straight into d_out), gather+combine
    k_gemm<64, 4><<<(M + 127) / 128, 256>>>((const float*)pH, Wl1, pHL, M);
    k_gemm<64, 4><<<(M + 127) / 128, 256>>>((const float*)pH, Wr1, (float*)d_out, M);
    k_gather64<<<(N_NODES * 32 + 255) / 256, 256>>>(bl1, (float*)d_out);
}

// round 13
// speedup vs baseline: 1.2321x; 1.0473x over previous
#include <cuda_runtime.h>
#include <cuda_bf16.h>
#include <cstdint>

#define N_NODES 100000
#define MAX_E 1600000
#define PADK 136                 // padded K stride (elems) for ldmatrix tiles

// ---------------- scratch (device globals; no allocation allowed) ----------
__device__ __align__(16) float g_XL[N_NODES * 128];
__device__ __align__(16) float g_XR[N_NODES * 128];
__device__ __align__(16) float g_H [N_NODES * 128];
__device__ __align__(16) float g_HL[N_NODES * 64];
__device__ int   g_cnt[N_NODES];
__device__ int   g_off[N_NODES];
__device__ int   g_cur[N_NODES];
__device__ int   g_eidx[MAX_E];
// W^T tiles [out][n][PADK] bf16, hi/lo planes, ready for ldmatrix
__device__ __align__(16) __nv_bfloat16 g_B0h[2 * 128 * PADK];
__device__ __align__(16) __nv_bfloat16 g_B0l[2 * 128 * PADK];
__device__ __align__(16) __nv_bfloat16 g_B1h[2 * 64 * PADK];
__device__ __align__(16) __nv_bfloat16 g_B1l[2 * 64 * PADK];

// ---------------- PTX helpers ------------------------------------------------
__device__ __forceinline__ uint32_t smem_u32(const void* p) {
    uint32_t a;
    asm("{ .reg .u64 t; cvta.to.shared.u64 t, %1; cvt.u32.u64 %0, t; }"
        : "=r"(a) : "l"(p));
    return a;
}
__device__ __forceinline__ void ldm4(uint32_t* r, uint32_t addr) {
    asm volatile("ldmatrix.sync.aligned.m8n8.x4.shared.b16 {%0,%1,%2,%3}, [%4];"
                 : "=r"(r[0]), "=r"(r[1]), "=r"(r[2]), "=r"(r[3]) : "r"(addr));
}
__device__ __forceinline__ void mma_bf16(float* d, const uint32_t* a,
                                         const uint32_t* b) {
    asm volatile(
        "mma.sync.aligned.m16n8k16.row.col.f32.bf16.bf16.f32 "
        "{%0,%1,%2,%3}, {%4,%5,%6,%7}, {%8,%9}, {%0,%1,%2,%3};"
        : "+f"(d[0]), "+f"(d[1]), "+f"(d[2]), "+f"(d[3])
        : "r"(a[0]), "r"(a[1]), "r"(a[2]), "r"(a[3]), "r"(b[0]), "r"(b[1]));
}

// ---------------- CSR build --------------------------------------------------
__global__ void k_zero() {
    int t = blockIdx.x * blockDim.x + threadIdx.x;
    if (t < N_NODES) { g_cnt[t] = 0; g_cur[t] = 0; }
}
__global__ void k_count(const int* __restrict__ dst, int E) {
    int t = blockIdx.x * blockDim.x + threadIdx.x;
    if (t < E) atomicAdd(&g_cnt[dst[t]], 1);
}
__global__ void __launch_bounds__(1024) k_scan() {
    __shared__ int sm[1024];
    const int t = threadIdx.x;
    const int CH = (N_NODES + 1023) / 1024;
    const int s0 = t * CH, s1 = min(s0 + CH, N_NODES);
    int sum = 0;
    for (int i = s0; i < s1; i++) sum += g_cnt[i];
    sm[t] = sum;
    __syncthreads();
    int val = sum;
    for (int off = 1; off < 1024; off <<= 1) {
        int other = (t >= off) ? sm[t - off] : 0;
        __syncthreads();
        val += other; sm[t] = val;
        __syncthreads();
    }
    int run = val - sum;
    for (int i = s0; i < s1; i++) { g_off[i] = run; run += g_cnt[i]; }
}
__global__ void k_fill(const int* __restrict__ src, const int* __restrict__ dst,
                       int E) {
    int t = blockIdx.x * blockDim.x + threadIdx.x;
    if (t >= E) return;
    int d = dst[t];
    int p = atomicAdd(&g_cur[d], 1);
    g_eidx[g_off[d] + p] = src[t];
}

// ---------------- weight conversion: W -> W^T [n][PADK], bf16 hi/lo ---------
__global__ void k_convW(const float* __restrict__ Wl0, const float* __restrict__ Wr0,
                        const float* __restrict__ Wl1, const float* __restrict__ Wr1) {
    int t = blockIdx.x * blockDim.x + threadIdx.x;
    if (t < 32768) {                       // layer 0: 2 outputs x 128n x 128k
        int w = t >> 14, e = t & 16383;
        int n = e >> 7, k = e & 127;
        float x = (w ? Wr0 : Wl0)[k * 128 + n];
        int idx = w * (128 * PADK) + n * PADK + k;
        __nv_bfloat16 h = __float2bfloat16(x);
        g_B0h[idx] = h;
        g_B0l[idx] = __float2bfloat16(x - __bfloat162float(h));
    } else if (t < 49152) {                // layer 1: 2 outputs x 64n x 128k
        int u = t - 32768;
        int w = u >> 13, e = u & 8191;
        int n = e >> 7, k = e & 127;
        float x = (w ? Wr1 : Wl1)[k * 64 + n];
        int idx = w * (64 * PADK) + n * PADK + k;
        __nv_bfloat16 h = __float2bfloat16(x);
        g_B1h[idx] = h;
        g_B1l[idx] = __float2bfloat16(x - __bfloat162float(h));
    }
}

// ---------------- bf16-split HMMA GEMM --------------------------------------
// C = A[M,128] @ W[128,BN] via 3 passes (AhBh + AhBl + AlBh), fp32 accum.
// blockIdx.y selects output 0/1 (B plane + C pointer). 256 thr, 8 warps (4m x 2n).
template<int BN>
__global__ void __launch_bounds__(256, 1)
k_mma(const float* __restrict__ A,
      const __nv_bfloat16* __restrict__ Bh, const __nv_bfloat16* __restrict__ Bl,
      float* __restrict__ C0, float* __restrict__ C1, int M)
{
    constexpr int NF = BN / 16;            // n-frags per warp (8 or 4)
    constexpr int RB = PADK * 2;           // row stride bytes = 272
    constexpr int SM_AH = 0, SM_AL = 128 * RB;
    constexpr int SM_BH = 2 * 128 * RB;
    constexpr int SM_BL = SM_BH + BN * RB;

    extern __shared__ char smem[];
    const uint32_t sb = smem_u32(smem);
    const int tid = threadIdx.x;
    const int wid = tid >> 5, lane = tid & 31;
    const int r0 = blockIdx.x * 128;
    float* C = blockIdx.y ? C1 : C0;
    const __nv_bfloat16* bhp = Bh + (size_t)blockIdx.y * BN * PADK;
    const __nv_bfloat16* blp = Bl + (size_t)blockIdx.y * BN * PADK;

    // ---- A: fp32 -> hi/lo bf16 into padded smem rows ----
    for (int i = tid; i < 4096; i += 256) {          // 128 rows x 32 float4
        int row = i >> 5, c4 = i & 31;
        int gr = r0 + row;
        float4 v = make_float4(0.f, 0.f, 0.f, 0.f);
        if (gr < M) v = *(const float4*)(A + (size_t)gr * 128 + c4 * 4);
        __nv_bfloat16 h0 = __float2bfloat16(v.x), h1 = __float2bfloat16(v.y);
        __nv_bfloat16 h2 = __float2bfloat16(v.z), h3 = __float2bfloat16(v.w);
        ushort4 hs = make_ushort4(__bfloat16_as_ushort(h0), __bfloat16_as_ushort(h1),
                                  __bfloat16_as_ushort(h2), __bfloat16_as_ushort(h3));
        ushort4 ls = make_ushort4(
            __bfloat16_as_ushort(__float2bfloat16(v.x - __bfloat162float(h0))),
            __bfloat16_as_ushort(__float2bfloat16(v.y - __bfloat162float(h1))),
            __bfloat16_as_ushort(__float2bfloat16(v.z - __bfloat162float(h2))),
            __bfloat16_as_ushort(__float2bfloat16(v.w - __bfloat162float(h3))));
        int off = row * RB + c4 * 8;
        *(ushort4*)(smem + SM_AH + off) = hs;
        *(ushort4*)(smem + SM_AL + off) = ls;
    }
    // ---- B: straight copy (already padded/transposed/split) ----
    {
        constexpr int NV = BN * 17;                  // uint4 per plane
        const uint4* sh = (const uint4*)bhp;
        const uint4* sl = (const uint4*)blp;
        uint4* dh = (uint4*)(smem + SM_BH);
        uint4* dl = (uint4*)(smem + SM_BL);
        for (int i = tid; i < NV; i += 256) { dh[i] = sh[i]; dl[i] = sl[i]; }
    }
    __syncthreads();

    const int m0 = (wid & 3) * 32;
    const int n0 = (wid >> 2) * (BN / 2);

    float acc[2][NF][4];
#pragma unroll
    for (int mi = 0; mi < 2; mi++)
#pragma unroll
        for (int nf = 0; nf < NF; nf++)
#pragma unroll
            for (int j = 0; j < 4; j++) acc[mi][nf][j] = 0.f;

    const int lrow = lane & 15;
    const int lcol = (lane >> 4) * 16;               // 8 elems * 2B

#pragma unroll 2
    for (int ks = 0; ks < 8; ks++) {
        const int kb = ks * 32;                      // k0 bytes

        uint32_t ah[2][4], al[2][4];
#pragma unroll
        for (int mi = 0; mi < 2; mi++) {
            uint32_t ad = sb + (m0 + mi * 16 + lrow) * RB + kb + lcol;
            ldm4(ah[mi], SM_AH + ad);
            ldm4(al[mi], SM_AL + ad);
        }
        uint32_t bh[NF][2], bl[NF][2];
#pragma unroll
        for (int p = 0; p < NF / 2; p++) {
            uint32_t ad = sb + (n0 + p * 16 + lrow) * RB + kb + lcol;
            uint32_t t[4];
            ldm4(t, SM_BH + ad);
            bh[2*p][0] = t[0]; bh[2*p][1] = t[2];
            bh[2*p+1][0] = t[1]; bh[2*p+1][1] = t[3];
            ldm4(t, SM_BL + ad);
            bl[2*p][0] = t[0]; bl[2*p][1] = t[2];
            bl[2*p+1][0] = t[1]; bl[2*p+1][1] = t[3];
        }
#pragma unroll
        for (int mi = 0; mi < 2; mi++)
#pragma unroll
            for (int nf = 0; nf < NF; nf++) {
                mma_bf16(acc[mi][nf], ah[mi], bh[nf]);
                mma_bf16(acc[mi][nf], ah[mi], bl[nf]);
                mma_bf16(acc[mi][nf], al[mi], bh[nf]);
            }
    }

    // ---- epilogue ----
#pragma unroll
    for (int mi = 0; mi < 2; mi++) {
        int rA = r0 + m0 + mi * 16 + (lane >> 2);
#pragma unroll
        for (int nf = 0; nf < NF; nf++) {
            int col = n0 + nf * 8 + (lane & 3) * 2;
            if (rA < M)
                *(float2*)(C + (size_t)rA * BN + col) = *(float2*)&acc[mi][nf][0];
            if (rA + 8 < M)
                *(float2*)(C + (size_t)(rA + 8) * BN + col) = *(float2*)&acc[mi][nf][2];
        }
    }
}

// ---------------- layer-0 gather: H = relu(mean(XL[nbrs]) + bl0 + XR) -------
__global__ void __launch_bounds__(256)
k_gather128(const float* __restrict__ bl0) {
    int warp = (blockIdx.x * blockDim.x + threadIdx.x) >> 5;
    int lane = threadIdx.x & 31;
    if (warp >= N_NODES) return;
    int deg = g_cnt[warp], base = g_off[warp];
    const float4* XL4 = (const float4*)g_XL;

    float4 acc = make_float4(0.f, 0.f, 0.f, 0.f);
    for (int i0 = 0; i0 < deg; i0 += 32) {
        int my  = (i0 + lane < deg) ? g_eidx[base + i0 + lane] : 0;
        int lim = min(32, deg - i0);
#pragma unroll 4
        for (int j = 0; j < lim; j++) {
            int s = __shfl_sync(0xffffffffu, my, j);
            float4 v = XL4[s * 32 + lane];
            acc.x += v.x; acc.y += v.y; acc.z += v.z; acc.w += v.w;
        }
    }
    float inv = 1.f / fmaxf((float)deg, 1.f);
    float4 b = ((const float4*)bl0)[lane];
    float4 x = ((const float4*)g_XR)[warp * 32 + lane];
    float4 r;
    r.x = fmaxf(fmaf(acc.x, inv, b.x) + x.x, 0.f);
    r.y = fmaxf(fmaf(acc.y, inv, b.y) + x.y, 0.f);
    r.z = fmaxf(fmaf(acc.z, inv, b.z) + x.z, 0.f);
    r.w = fmaxf(fmaf(acc.w, inv, b.w) + x.w, 0.f);
    ((float4*)g_H)[warp * 32 + lane] = r;
}

// ---------------- layer-1 gather: out += mean(HL[nbrs]) + bl1 ---------------
__global__ void __launch_bounds__(256)
k_gather64(const float* __restrict__ bl1, float* __restrict__ out) {
    int warp = (blockIdx.x * blockDim.x + threadIdx.x) >> 5;
    int lane = threadIdx.x & 31;
    if (warp >= N_NODES) return;
    int deg = g_cnt[warp], base = g_off[warp];

    const float2* H2 = (const float2*)g_HL;
    float2 acc = make_float2(0.f, 0.f);
    for (int i0 = 0; i0 < deg; i0 += 32) {
        int my  = (i0 + lane < deg) ? g_eidx[base + i0 + lane] : 0;
        int lim = min(32, deg - i0);
#pragma unroll 4
        for (int j = 0; j < lim; j++) {
            int s = __shfl_sync(0xffffffffu, my, j);
            float2 v = H2[s * 32 + lane];
            acc.x += v.x; acc.y += v.y;
        }
    }
    float inv = 1.f / fmaxf((float)deg, 1.f);
    float2 b = ((const float2*)bl1)[lane];
    float2* out2 = (float2*)out;
    float2 o = out2[warp * 32 + lane];
    o.x += fmaf(acc.x, inv, b.x);
    o.y += fmaf(acc.y, inv, b.y);
    out2[warp * 32 + lane] = o;
}

// ---------------- launch -----------------------------------------------------
extern "C" void kernel_launch(void* const* d_in, const int* in_sizes, int n_in,
                              void* d_out, int out_size) {
    const float* x   = (const float*)d_in[0];
    const int*   ei  = (const int*)d_in[1];
    const float* Wl0 = (const float*)d_in[2];
    const float* bl0 = (const float*)d_in[3];
    const float* Wr0 = (const float*)d_in[4];
    const float* Wl1 = (const float*)d_in[5];
    const float* bl1 = (const float*)d_in[6];
    const float* Wr1 = (const float*)d_in[7];

    const int E = in_sizes[1] / 2;
    const int* src = ei;
    const int* dst = ei + E;
    const int M = N_NODES;

    float *pXL, *pXR, *pH, *pHL;
    __nv_bfloat16 *pB0h, *pB0l, *pB1h, *pB1l;
    cudaGetSymbolAddress((void**)&pXL, g_XL);
    cudaGetSymbolAddress((void**)&pXR, g_XR);
    cudaGetSymbolAddress((void**)&pH,  g_H);
    cudaGetSymbolAddress((void**)&pHL, g_HL);
    cudaGetSymbolAddress((void**)&pB0h, g_B0h);
    cudaGetSymbolAddress((void**)&pB0l, g_B0l);
    cudaGetSymbolAddress((void**)&pB1h, g_B1h);
    cudaGetSymbolAddress((void**)&pB1l, g_B1l);

    constexpr int RB = PADK * 2;
    constexpr int SMEM0 = 2 * 128 * RB + 2 * 128 * RB;   // 139264
    constexpr int SMEM1 = 2 * 128 * RB + 2 * 64 * RB;    // 104448
    cudaFuncSetAttribute(k_mma<128>, cudaFuncAttributeMaxDynamicSharedMemorySize, SMEM0);
    cudaFuncSetAttribute(k_mma<64>,  cudaFuncAttributeMaxDynamicSharedMemorySize, SMEM1);

    // CSR build + weight conversion
    k_zero<<<(N_NODES + 255) / 256, 256>>>();
    k_count<<<(E + 255) / 256, 256>>>(dst, E);
    k_scan<<<1, 1024>>>();
    k_fill<<<(E + 255) / 256, 256>>>(src, dst, E);
    k_convW<<<192, 256>>>(Wl0, Wr0, Wl1, Wr1);

    const int GB = (M + 127) / 128;                      // 782
    dim3 grid0(GB, 2), grid1(GB, 2);
    // layer 0: y=0 -> XL (Wl0), y=1 -> XR (Wr0)
    k_mma<128><<<grid0, 256, SMEM0>>>(x, pB0h, pB0l, pXL, pXR, M);
    k_gather128<<<(N_NODES * 32 + 255) / 256, 256>>>(bl0);
    // layer 1: y=0 -> HL (Wl1), y=1 -> d_out (Wr1 root term)
    k_mma<64><<<grid1, 256, SMEM1>>>((const float*)pH, pB1h, pB1l, pHL, (float*)d_out, M);
    k_gather64<<<(N_NODES * 32 + 255) / 256, 256>>>(bl1, (float*)d_out);
}

// round 15
// speedup vs baseline: 1.5968x; 1.2961x over previous
#include <cuda_runtime.h>
#include <cuda_bf16.h>
#include <cstdint>

#define N_NODES 100000
#define MAX_E 1600000
#define PADK 136                 // padded K stride (elems); row = 272B = 17 uint4

// ---------------- scratch (device globals; no allocation allowed) ----------
__device__ __align__(16) float g_XL[N_NODES * 128];
__device__ __align__(16) float g_XR[N_NODES * 128];
__device__ __align__(16) float g_H [N_NODES * 128];
__device__ __align__(16) float g_HL[N_NODES * 64];
__device__ int   g_cnt[N_NODES];
__device__ int   g_off[N_NODES];
__device__ int   g_cur[N_NODES];
__device__ int   g_eidx[MAX_E];
// W^T tiles [out][n][PADK] bf16, hi/lo planes, ready for ldmatrix
__device__ __align__(16) __nv_bfloat16 g_B0h[2 * 128 * PADK];
__device__ __align__(16) __nv_bfloat16 g_B0l[2 * 128 * PADK];
__device__ __align__(16) __nv_bfloat16 g_B1h[2 * 64 * PADK];
__device__ __align__(16) __nv_bfloat16 g_B1l[2 * 64 * PADK];

// ---------------- PTX helpers ------------------------------------------------
__device__ __forceinline__ uint32_t smem_u32(const void* p) {
    uint32_t a;
    asm("{ .reg .u64 t; cvta.to.shared.u64 t, %1; cvt.u32.u64 %0, t; }"
        : "=r"(a) : "l"(p));
    return a;
}
__device__ __forceinline__ void ldm4(uint32_t* r, uint32_t addr) {
    asm volatile("ldmatrix.sync.aligned.m8n8.x4.shared.b16 {%0,%1,%2,%3}, [%4];"
                 : "=r"(r[0]), "=r"(r[1]), "=r"(r[2]), "=r"(r[3]) : "r"(addr));
}
__device__ __forceinline__ void mma_bf16(float* d, const uint32_t* a,
                                         const uint32_t* b) {
    asm volatile(
        "mma.sync.aligned.m16n8k16.row.col.f32.bf16.bf16.f32 "
        "{%0,%1,%2,%3}, {%4,%5,%6,%7}, {%8,%9}, {%0,%1,%2,%3};"
        : "+f"(d[0]), "+f"(d[1]), "+f"(d[2]), "+f"(d[3])
        : "r"(a[0]), "r"(a[1]), "r"(a[2]), "r"(a[3]), "r"(b[0]), "r"(b[1]));
}

// ---------------- CSR build --------------------------------------------------
__global__ void k_zero() {
    int t = blockIdx.x * blockDim.x + threadIdx.x;
    if (t < N_NODES) { g_cnt[t] = 0; g_cur[t] = 0; }
}
__global__ void k_count(const int* __restrict__ dst, int E) {
    int t = blockIdx.x * blockDim.x + threadIdx.x;
    if (t < E) atomicAdd(&g_cnt[dst[t]], 1);
}
__global__ void __launch_bounds__(1024) k_scan() {
    __shared__ int sm[1024];
    const int t = threadIdx.x;
    const int CH = (N_NODES + 1023) / 1024;
    const int s0 = t * CH, s1 = min(s0 + CH, N_NODES);
    int sum = 0;
    for (int i = s0; i < s1; i++) sum += g_cnt[i];
    sm[t] = sum;
    __syncthreads();
    int val = sum;
    for (int off = 1; off < 1024; off <<= 1) {
        int other = (t >= off) ? sm[t - off] : 0;
        __syncthreads();
        val += other; sm[t] = val;
        __syncthreads();
    }
    int run = val - sum;
    for (int i = s0; i < s1; i++) { g_off[i] = run; run += g_cnt[i]; }
}
__global__ void k_fill(const int* __restrict__ src, const int* __restrict__ dst,
                       int E) {
    int t = blockIdx.x * blockDim.x + threadIdx.x;
    if (t >= E) return;
    int d = dst[t];
    int p = atomicAdd(&g_cur[d], 1);
    g_eidx[g_off[d] + p] = src[t];
}

// ---------------- weight conversion: W -> W^T [n][PADK], bf16 hi/lo ---------
__global__ void k_convW(const float* __restrict__ Wl0, const float* __restrict__ Wr0,
                        const float* __restrict__ Wl1, const float* __restrict__ Wr1) {
    int t = blockIdx.x * blockDim.x + threadIdx.x;
    if (t < 32768) {                       // layer 0: 2 outputs x 128n x 128k
        int w = t >> 14, e = t & 16383;
        int n = e >> 7, k = e & 127;
        float x = (w ? Wr0 : Wl0)[k * 128 + n];
        int idx = w * (128 * PADK) + n * PADK + k;
        __nv_bfloat16 h = __float2bfloat16(x);
        g_B0h[idx] = h;
        g_B0l[idx] = __float2bfloat16(x - __bfloat162float(h));
    } else if (t < 49152) {                // layer 1: 2 outputs x 64n x 128k
        int u = t - 32768;
        int w = u >> 13, e = u & 8191;
        int n = e >> 7, k = e & 127;
        float x = (w ? Wr1 : Wl1)[k * 64 + n];
        int idx = w * (64 * PADK) + n * PADK + k;
        __nv_bfloat16 h = __float2bfloat16(x);
        g_B1h[idx] = h;
        g_B1l[idx] = __float2bfloat16(x - __bfloat162float(h));
    }
}

// ---------------- persistent bf16-split HMMA GEMM ---------------------------
// Each CTA keeps ALL B planes (2 outputs x hi/lo) in smem and loops over
// 64-row A tiles.  Per tile: stage A (hi/lo bf16), compute both outputs.
// 8 warps = 2m x 4n; warp tile 32 x BN/4.
template<int BN>
__global__ void __launch_bounds__(256)
k_mma(const float* __restrict__ A,
      const __nv_bfloat16* __restrict__ Bh, const __nv_bfloat16* __restrict__ Bl,
      float* __restrict__ C0, float* __restrict__ C1, int M, int nTiles)
{
    constexpr int RB = PADK * 2;           // 272 bytes per row
    constexpr int ROWS = 64;
    constexpr int NF = BN / 32;            // 8-col frags per warp (4 or 2)
    constexpr int SM_AH = 0, SM_AL = ROWS * RB;
    constexpr int SM_B = 2 * ROWS * RB;    // 34816

    extern __shared__ char smem[];
    const uint32_t sb = smem_u32(smem);
    const int tid = threadIdx.x;
    const int wid = tid >> 5, lane = tid & 31;
    const int m0 = (wid & 1) * 32;
    const int n0 = (wid >> 1) * (BN / 4);
    const int lrow = lane & 15;
    const int lcol = (lane >> 4) * 16;

    // ---- B: copy all 4 planes once (source rows already PADK-padded) ----
    {
        constexpr int PV = BN * 17;                     // uint4 per plane
        const uint4* shp = (const uint4*)Bh;
        const uint4* slp = (const uint4*)Bl;
        uint4* d = (uint4*)(smem + SM_B);
        for (int i = tid; i < 2 * PV; i += 256) {       // i over [y][n][17]
            int y = i / PV, w = i - y * PV;
            d[(y * 2 + 0) * PV + w] = shp[i];
            d[(y * 2 + 1) * PV + w] = slp[i];
        }
    }

    for (int t = blockIdx.x; t < nTiles; t += gridDim.x) {
        const int r0 = t * ROWS;

        // ---- stage next A tile into regs (LDG latency overlaps the sync) --
        float4 v[8];
#pragma unroll
        for (int j = 0; j < 8; j++) {
            int i = tid + j * 256;                      // 0..2047
            int row = i >> 5, c4 = i & 31;
            int gr = r0 + row;
            v[j] = make_float4(0.f, 0.f, 0.f, 0.f);
            if (gr < M) v[j] = *(const float4*)(A + (size_t)gr * 128 + c4 * 4);
        }
        __syncthreads();                                // prev tile's reads done
#pragma unroll
        for (int j = 0; j < 8; j++) {
            int i = tid + j * 256;
            int row = i >> 5, c4 = i & 31;
            __nv_bfloat16 h0 = __float2bfloat16(v[j].x), h1 = __float2bfloat16(v[j].y);
            __nv_bfloat16 h2 = __float2bfloat16(v[j].z), h3 = __float2bfloat16(v[j].w);
            ushort4 hs = make_ushort4(__bfloat16_as_ushort(h0), __bfloat16_as_ushort(h1),
                                      __bfloat16_as_ushort(h2), __bfloat16_as_ushort(h3));
            ushort4 ls = make_ushort4(
                __bfloat16_as_ushort(__float2bfloat16(v[j].x - __bfloat162float(h0))),
                __bfloat16_as_ushort(__float2bfloat16(v[j].y - __bfloat162float(h1))),
                __bfloat16_as_ushort(__float2bfloat16(v[j].z - __bfloat162float(h2))),
                __bfloat16_as_ushort(__float2bfloat16(v[j].w - __bfloat162float(h3))));
            int off = row * RB + c4 * 8;
            *(ushort4*)(smem + SM_AH + off) = hs;
            *(ushort4*)(smem + SM_AL + off) = ls;
        }
        __syncthreads();

        // ---- compute both outputs from this A tile ----
#pragma unroll
        for (int y = 0; y < 2; y++) {
            const uint32_t bsH = sb + SM_B + (y * 2 + 0) * BN * RB;
            const uint32_t bsL = sb + SM_B + (y * 2 + 1) * BN * RB;
            float* C = y ? C1 : C0;

            float acc[2][NF][4];
#pragma unroll
            for (int mi = 0; mi < 2; mi++)
#pragma unroll
                for (int nf = 0; nf < NF; nf++)
#pragma unroll
                    for (int j = 0; j < 4; j++) acc[mi][nf][j] = 0.f;

#pragma unroll
            for (int ks = 0; ks < 8; ks++) {
                const int kb = ks * 32;
                uint32_t ah[2][4], al[2][4];
#pragma unroll
                for (int mi = 0; mi < 2; mi++) {
                    uint32_t ad = sb + (m0 + mi * 16 + lrow) * RB + kb + lcol;
                    ldm4(ah[mi], SM_AH + ad);
                    ldm4(al[mi], SM_AL + ad);
                }
                uint32_t bh[NF][2], bl[NF][2];
#pragma unroll
                for (int p = 0; p < NF / 2; p++) {
                    uint32_t ad = (n0 + p * 16 + lrow) * RB + kb + lcol;
                    uint32_t q[4];
                    ldm4(q, bsH + ad);
                    bh[2*p][0] = q[0]; bh[2*p][1] = q[2];
                    bh[2*p+1][0] = q[1]; bh[2*p+1][1] = q[3];
                    ldm4(q, bsL + ad);
                    bl[2*p][0] = q[0]; bl[2*p][1] = q[2];
                    bl[2*p+1][0] = q[1]; bl[2*p+1][1] = q[3];
                }
#pragma unroll
                for (int mi = 0; mi < 2; mi++)
#pragma unroll
                    for (int nf = 0; nf < NF; nf++) {
                        mma_bf16(acc[mi][nf], ah[mi], bh[nf]);
                        mma_bf16(acc[mi][nf], ah[mi], bl[nf]);
                        mma_bf16(acc[mi][nf], al[mi], bh[nf]);
                    }
            }

            // ---- epilogue ----
#pragma unroll
            for (int mi = 0; mi < 2; mi++) {
                int rA = r0 + m0 + mi * 16 + (lane >> 2);
#pragma unroll
                for (int nf = 0; nf < NF; nf++) {
                    int col = n0 + nf * 8 + (lane & 3) * 2;
                    if (rA < M)
                        *(float2*)(C + (size_t)rA * BN + col) = *(float2*)&acc[mi][nf][0];
                    if (rA + 8 < M)
                        *(float2*)(C + (size_t)(rA + 8) * BN + col) = *(float2*)&acc[mi][nf][2];
                }
            }
        }
    }
}

// ---------------- layer-0 gather: H = relu(mean(XL[nbrs]) + bl0 + XR) -------
__global__ void __launch_bounds__(256)
k_gather128(const float* __restrict__ bl0) {
    int warp = (blockIdx.x * blockDim.x + threadIdx.x) >> 5;
    int lane = threadIdx.x & 31;
    if (warp >= N_NODES) return;
    int deg = g_cnt[warp], base = g_off[warp];
    const float4* XL4 = (const float4*)g_XL;

    float4 acc = make_float4(0.f, 0.f, 0.f, 0.f);
    for (int i0 = 0; i0 < deg; i0 += 32) {
        int my  = (i0 + lane < deg) ? g_eidx[base + i0 + lane] : 0;
        int lim = min(32, deg - i0);
#pragma unroll 4
        for (int j = 0; j < lim; j++) {
            int s = __shfl_sync(0xffffffffu, my, j);
            float4 v = XL4[s * 32 + lane];
            acc.x += v.x; acc.y += v.y; acc.z += v.z; acc.w += v.w;
        }
    }
    float inv = 1.f / fmaxf((float)deg, 1.f);
    float4 b = ((const float4*)bl0)[lane];
    float4 x = ((const float4*)g_XR)[warp * 32 + lane];
    float4 r;
    r.x = fmaxf(fmaf(acc.x, inv, b.x) + x.x, 0.f);
    r.y = fmaxf(fmaf(acc.y, inv, b.y) + x.y, 0.f);
    r.z = fmaxf(fmaf(acc.z, inv, b.z) + x.z, 0.f);
    r.w = fmaxf(fmaf(acc.w, inv, b.w) + x.w, 0.f);
    ((float4*)g_H)[warp * 32 + lane] = r;
}

// ---------------- layer-1 gather: out += mean(HL[nbrs]) + bl1 ---------------
__global__ void __launch_bounds__(256)
k_gather64(const float* __restrict__ bl1, float* __restrict__ out) {
    int warp = (blockIdx.x * blockDim.x + threadIdx.x) >> 5;
    int lane = threadIdx.x & 31;
    if (warp >= N_NODES) return;
    int deg = g_cnt[warp], base = g_off[warp];

    const float2* H2 = (const float2*)g_HL;
    float2 acc = make_float2(0.f, 0.f);
    for (int i0 = 0; i0 < deg; i0 += 32) {
        int my  = (i0 + lane < deg) ? g_eidx[base + i0 + lane] : 0;
        int lim = min(32, deg - i0);
#pragma unroll 4
        for (int j = 0; j < lim; j++) {
            int s = __shfl_sync(0xffffffffu, my, j);
            float2 v = H2[s * 32 + lane];
            acc.x += v.x; acc.y += v.y;
        }
    }
    float inv = 1.f / fmaxf((float)deg, 1.f);
    float2 b = ((const float2*)bl1)[lane];
    float2* out2 = (float2*)out;
    float2 o = out2[warp * 32 + lane];
    o.x += fmaf(acc.x, inv, b.x);
    o.y += fmaf(acc.y, inv, b.y);
    out2[warp * 32 + lane] = o;
}

// ---------------- launch -----------------------------------------------------
extern "C" void kernel_launch(void* const* d_in, const int* in_sizes, int n_in,
                              void* d_out, int out_size) {
    const float* x   = (const float*)d_in[0];
    const int*   ei  = (const int*)d_in[1];
    const float* Wl0 = (const float*)d_in[2];
    const float* bl0 = (const float*)d_in[3];
    const float* Wr0 = (const float*)d_in[4];
    const float* Wl1 = (const float*)d_in[5];
    const float* bl1 = (const float*)d_in[6];
    const float* Wr1 = (const float*)d_in[7];

    const int E = in_sizes[1] / 2;
    const int* src = ei;
    const int* dst = ei + E;
    const int M = N_NODES;
    const int nTiles = (M + 63) / 64;                    // 1563

    float *pXL, *pXR, *pH, *pHL;
    __nv_bfloat16 *pB0h, *pB0l, *pB1h, *pB1l;
    cudaGetSymbolAddress((void**)&pXL, g_XL);
    cudaGetSymbolAddress((void**)&pXR, g_XR);
    cudaGetSymbolAddress((void**)&pH,  g_H);
    cudaGetSymbolAddress((void**)&pHL, g_HL);
    cudaGetSymbolAddress((void**)&pB0h, g_B0h);
    cudaGetSymbolAddress((void**)&pB0l, g_B0l);
    cudaGetSymbolAddress((void**)&pB1h, g_B1h);
    cudaGetSymbolAddress((void**)&pB1l, g_B1l);

    constexpr int RB = PADK * 2;
    constexpr int SMEM0 = 2 * 64 * RB + 4 * 128 * RB;    // 174080
    constexpr int SMEM1 = 2 * 64 * RB + 4 * 64 * RB;     // 104448
    cudaFuncSetAttribute(k_mma<128>, cudaFuncAttributeMaxDynamicSharedMemorySize, SMEM0);
    cudaFuncSetAttribute(k_mma<64>,  cudaFuncAttributeMaxDynamicSharedMemorySize, SMEM1);

    // CSR build + weight conversion
    k_zero<<<(N_NODES + 255) / 256, 256>>>();
    k_count<<<(E + 255) / 256, 256>>>(dst, E);
    k_scan<<<1, 1024>>>();
    k_fill<<<(E + 255) / 256, 256>>>(src, dst, E);
    k_convW<<<192, 256>>>(Wl0, Wr0, Wl1, Wr1);

    // layer 0: persistent GEMM (both outputs), then gather+combine
    k_mma<128><<<148, 256, SMEM0>>>(x, pB0h, pB0l, pXL, pXR, M, nTiles);
    k_gather128<<<(N_NODES * 32 + 255) / 256, 256>>>(bl0);
    // layer 1: persistent GEMM (HL + root term into d_out), then gather
    k_mma<64><<<296, 256, SMEM1>>>((const float*)pH, pB1h, pB1l, pHL,
                                   (float*)d_out, M, nTiles);
    k_gather64<<<(N_NODES * 32 + 255) / 256, 256>>>(bl1, (float*)d_out);
}

// round 16
// speedup vs baseline: 1.6460x; 1.0308x over previous
#include <cuda_runtime.h>
#include <cuda_bf16.h>
#include <cuda_fp16.h>
#include <cstdint>

#define N_NODES 100000
#define MAX_E 1600000
#define PADK 136                 // padded K stride (elems); row = 272B = 17 uint4

// ---------------- scratch (device globals; no allocation allowed) ----------
__device__ __align__(16) __half g_XL[N_NODES * 128];  // x@Wl0, fp16 (gathered)
__device__ __align__(16) float  g_XR[N_NODES * 128];  // x@Wr0, fp32
__device__ __align__(16) float  g_H [N_NODES * 128];  // hidden, fp32
__device__ __align__(16) __half g_HL[N_NODES * 64];   // h@Wl1, fp16 (gathered)
__device__ int   g_cnt[N_NODES];
__device__ int   g_off[N_NODES];
__device__ int   g_cur[N_NODES];
__device__ int   g_eidx[MAX_E];
// W^T tiles [out][n][PADK] bf16, hi/lo planes, ready for ldmatrix
__device__ __align__(16) __nv_bfloat16 g_B0h[2 * 128 * PADK];
__device__ __align__(16) __nv_bfloat16 g_B0l[2 * 128 * PADK];
__device__ __align__(16) __nv_bfloat16 g_B1h[2 * 64 * PADK];
__device__ __align__(16) __nv_bfloat16 g_B1l[2 * 64 * PADK];

// ---------------- PTX helpers ------------------------------------------------
__device__ __forceinline__ uint32_t smem_u32(const void* p) {
    uint32_t a;
    asm("{ .reg .u64 t; cvta.to.shared.u64 t, %1; cvt.u32.u64 %0, t; }"
        : "=r"(a) : "l"(p));
    return a;
}
__device__ __forceinline__ void ldm4(uint32_t* r, uint32_t addr) {
    asm volatile("ldmatrix.sync.aligned.m8n8.x4.shared.b16 {%0,%1,%2,%3}, [%4];"
                 : "=r"(r[0]), "=r"(r[1]), "=r"(r[2]), "=r"(r[3]) : "r"(addr));
}
__device__ __forceinline__ void mma_bf16(float* d, const uint32_t* a,
                                         const uint32_t* b) {
    asm volatile(
        "mma.sync.aligned.m16n8k16.row.col.f32.bf16.bf16.f32 "
        "{%0,%1,%2,%3}, {%4,%5,%6,%7}, {%8,%9}, {%0,%1,%2,%3};"
        : "+f"(d[0]), "+f"(d[1]), "+f"(d[2]), "+f"(d[3])
        : "r"(a[0]), "r"(a[1]), "r"(a[2]), "r"(a[3]), "r"(b[0]), "r"(b[1]));
}

// ---------------- CSR build --------------------------------------------------
__global__ void k_zero() {
    int t = blockIdx.x * blockDim.x + threadIdx.x;
    if (t < N_NODES) { g_cnt[t] = 0; g_cur[t] = 0; }
}
__global__ void k_count(const int* __restrict__ dst, int E) {
    int t = blockIdx.x * blockDim.x + threadIdx.x;
    if (t < E) atomicAdd(&g_cnt[dst[t]], 1);
}
__global__ void __launch_bounds__(1024) k_scan() {
    __shared__ int sm[1024];
    const int t = threadIdx.x;
    const int CH = (N_NODES + 1023) / 1024;
    const int s0 = t * CH, s1 = min(s0 + CH, N_NODES);
    int sum = 0;
    for (int i = s0; i < s1; i++) sum += g_cnt[i];
    sm[t] = sum;
    __syncthreads();
    int val = sum;
    for (int off = 1; off < 1024; off <<= 1) {
        int other = (t >= off) ? sm[t - off] : 0;
        __syncthreads();
        val += other; sm[t] = val;
        __syncthreads();
    }
    int run = val - sum;
    for (int i = s0; i < s1; i++) { g_off[i] = run; run += g_cnt[i]; }
}
__global__ void k_fill(const int* __restrict__ src, const int* __restrict__ dst,
                       int E) {
    int t = blockIdx.x * blockDim.x + threadIdx.x;
    if (t >= E) return;
    int d = dst[t];
    int p = atomicAdd(&g_cur[d], 1);
    g_eidx[g_off[d] + p] = src[t];
}

// ---------------- weight conversion: W -> W^T [n][PADK], bf16 hi/lo ---------
__global__ void k_convW(const float* __restrict__ Wl0, const float* __restrict__ Wr0,
                        const float* __restrict__ Wl1, const float* __restrict__ Wr1) {
    int t = blockIdx.x * blockDim.x + threadIdx.x;
    if (t < 32768) {                       // layer 0: 2 outputs x 128n x 128k
        int w = t >> 14, e = t & 16383;
        int n = e >> 7, k = e & 127;
        float x = (w ? Wr0 : Wl0)[k * 128 + n];
        int idx = w * (128 * PADK) + n * PADK + k;
        __nv_bfloat16 h = __float2bfloat16(x);
        g_B0h[idx] = h;
        g_B0l[idx] = __float2bfloat16(x - __bfloat162float(h));
    } else if (t < 49152) {                // layer 1: 2 outputs x 64n x 128k
        int u = t - 32768;
        int w = u >> 13, e = u & 8191;
        int n = e >> 7, k = e & 127;
        float x = (w ? Wr1 : Wl1)[k * 64 + n];
        int idx = w * (64 * PADK) + n * PADK + k;
        __nv_bfloat16 h = __float2bfloat16(x);
        g_B1h[idx] = h;
        g_B1l[idx] = __float2bfloat16(x - __bfloat162float(h));
    }
}

// ---------------- persistent bf16-split HMMA GEMM ---------------------------
// Output 0 (gathered operand) is written fp16; output 1 fp32.
// 8 warps = 2m x 4n; 64-row A tiles, all 4 B planes resident in smem.
template<int BN>
__global__ void __launch_bounds__(256)
k_mma(const float* __restrict__ A,
      const __nv_bfloat16* __restrict__ Bh, const __nv_bfloat16* __restrict__ Bl,
      __half* __restrict__ C0, float* __restrict__ C1, int M, int nTiles)
{
    constexpr int RB = PADK * 2;           // 272 bytes per row
    constexpr int ROWS = 64;
    constexpr int NF = BN / 32;            // 8-col frags per warp (4 or 2)
    constexpr int SM_AH = 0, SM_AL = ROWS * RB;
    constexpr int SM_B = 2 * ROWS * RB;    // 34816

    extern __shared__ char smem[];
    const uint32_t sb = smem_u32(smem);
    const int tid = threadIdx.x;
    const int wid = tid >> 5, lane = tid & 31;
    const int m0 = (wid & 1) * 32;
    const int n0 = (wid >> 1) * (BN / 4);
    const int lrow = lane & 15;
    const int lcol = (lane >> 4) * 16;

    // ---- B: copy all 4 planes once ----
    {
        constexpr int PV = BN * 17;                     // uint4 per plane
        const uint4* shp = (const uint4*)Bh;
        const uint4* slp = (const uint4*)Bl;
        uint4* d = (uint4*)(smem + SM_B);
        for (int i = tid; i < 2 * PV; i += 256) {
            int y = i / PV, w = i - y * PV;
            d[(y * 2 + 0) * PV + w] = shp[i];
            d[(y * 2 + 1) * PV + w] = slp[i];
        }
    }

    for (int t = blockIdx.x; t < nTiles; t += gridDim.x) {
        const int r0 = t * ROWS;

        float4 v[8];
#pragma unroll
        for (int j = 0; j < 8; j++) {
            int i = tid + j * 256;
            int row = i >> 5, c4 = i & 31;
            int gr = r0 + row;
            v[j] = make_float4(0.f, 0.f, 0.f, 0.f);
            if (gr < M) v[j] = *(const float4*)(A + (size_t)gr * 128 + c4 * 4);
        }
        __syncthreads();
#pragma unroll
        for (int j = 0; j < 8; j++) {
            int i = tid + j * 256;
            int row = i >> 5, c4 = i & 31;
            __nv_bfloat16 h0 = __float2bfloat16(v[j].x), h1 = __float2bfloat16(v[j].y);
            __nv_bfloat16 h2 = __float2bfloat16(v[j].z), h3 = __float2bfloat16(v[j].w);
            ushort4 hs = make_ushort4(__bfloat16_as_ushort(h0), __bfloat16_as_ushort(h1),
                                      __bfloat16_as_ushort(h2), __bfloat16_as_ushort(h3));
            ushort4 ls = make_ushort4(
                __bfloat16_as_ushort(__float2bfloat16(v[j].x - __bfloat162float(h0))),
                __bfloat16_as_ushort(__float2bfloat16(v[j].y - __bfloat162float(h1))),
                __bfloat16_as_ushort(__float2bfloat16(v[j].z - __bfloat162float(h2))),
                __bfloat16_as_ushort(__float2bfloat16(v[j].w - __bfloat162float(h3))));
            int off = row * RB + c4 * 8;
            *(ushort4*)(smem + SM_AH + off) = hs;
            *(ushort4*)(smem + SM_AL + off) = ls;
        }
        __syncthreads();

#pragma unroll
        for (int y = 0; y < 2; y++) {
            const uint32_t bsH = sb + SM_B + (y * 2 + 0) * BN * RB;
            const uint32_t bsL = sb + SM_B + (y * 2 + 1) * BN * RB;

            float acc[2][NF][4];
#pragma unroll
            for (int mi = 0; mi < 2; mi++)
#pragma unroll
                for (int nf = 0; nf < NF; nf++)
#pragma unroll
                    for (int j = 0; j < 4; j++) acc[mi][nf][j] = 0.f;

#pragma unroll
            for (int ks = 0; ks < 8; ks++) {
                const int kb = ks * 32;
                uint32_t ah[2][4], al[2][4];
#pragma unroll
                for (int mi = 0; mi < 2; mi++) {
                    uint32_t ad = sb + (m0 + mi * 16 + lrow) * RB + kb + lcol;
                    ldm4(ah[mi], SM_AH + ad);
                    ldm4(al[mi], SM_AL + ad);
                }
                uint32_t bh[NF][2], bl[NF][2];
#pragma unroll
                for (int p = 0; p < NF / 2; p++) {
                    uint32_t ad = (n0 + p * 16 + lrow) * RB + kb + lcol;
                    uint32_t q[4];
                    ldm4(q, bsH + ad);
                    bh[2*p][0] = q[0]; bh[2*p][1] = q[2];
                    bh[2*p+1][0] = q[1]; bh[2*p+1][1] = q[3];
                    ldm4(q, bsL + ad);
                    bl[2*p][0] = q[0]; bl[2*p][1] = q[2];
                    bl[2*p+1][0] = q[1]; bl[2*p+1][1] = q[3];
                }
#pragma unroll
                for (int mi = 0; mi < 2; mi++)
#pragma unroll
                    for (int nf = 0; nf < NF; nf++) {
                        mma_bf16(acc[mi][nf], ah[mi], bh[nf]);
                        mma_bf16(acc[mi][nf], ah[mi], bl[nf]);
                        mma_bf16(acc[mi][nf], al[mi], bh[nf]);
                    }
            }

            // ---- epilogue: y=0 -> fp16 C0, y=1 -> fp32 C1 ----
#pragma unroll
            for (int mi = 0; mi < 2; mi++) {
                int rA = r0 + m0 + mi * 16 + (lane >> 2);
#pragma unroll
                for (int nf = 0; nf < NF; nf++) {
                    int col = n0 + nf * 8 + (lane & 3) * 2;
                    if (y == 0) {
                        if (rA < M)
                            *(__half2*)(C0 + (size_t)rA * BN + col) =
                                __floats2half2_rn(acc[mi][nf][0], acc[mi][nf][1]);
                        if (rA + 8 < M)
                            *(__half2*)(C0 + (size_t)(rA + 8) * BN + col) =
                                __floats2half2_rn(acc[mi][nf][2], acc[mi][nf][3]);
                    } else {
                        if (rA < M)
                            *(float2*)(C1 + (size_t)rA * BN + col) = *(float2*)&acc[mi][nf][0];
                        if (rA + 8 < M)
                            *(float2*)(C1 + (size_t)(rA + 8) * BN + col) = *(float2*)&acc[mi][nf][2];
                    }
                }
            }
        }
    }
}

// ---------------- layer-0 gather: H = relu(mean(XL[nbrs]) + bl0 + XR) -------
// lane c holds columns 4c..4c+3 (half4 = uint2), accumulate fp32
__global__ void __launch_bounds__(256)
k_gather128(const float* __restrict__ bl0) {
    int warp = (blockIdx.x * blockDim.x + threadIdx.x) >> 5;
    int lane = threadIdx.x & 31;
    if (warp >= N_NODES) return;
    int deg = g_cnt[warp], base = g_off[warp];
    const uint2* XL2 = (const uint2*)g_XL;   // 32 uint2 per row

    float4 acc = make_float4(0.f, 0.f, 0.f, 0.f);
    for (int i0 = 0; i0 < deg; i0 += 32) {
        int my  = (i0 + lane < deg) ? g_eidx[base + i0 + lane] : 0;
        int lim = min(32, deg - i0);
#pragma unroll 4
        for (int j = 0; j < lim; j++) {
            int s = __shfl_sync(0xffffffffu, my, j);
            uint2 u = XL2[s * 32 + lane];
            float2 f0 = __half22float2(*(const __half2*)&u.x);
            float2 f1 = __half22float2(*(const __half2*)&u.y);
            acc.x += f0.x; acc.y += f0.y; acc.z += f1.x; acc.w += f1.y;
        }
    }
    float inv = 1.f / fmaxf((float)deg, 1.f);
    float4 b = ((const float4*)bl0)[lane];
    float4 x = ((const float4*)g_XR)[warp * 32 + lane];
    float4 r;
    r.x = fmaxf(fmaf(acc.x, inv, b.x) + x.x, 0.f);
    r.y = fmaxf(fmaf(acc.y, inv, b.y) + x.y, 0.f);
    r.z = fmaxf(fmaf(acc.z, inv, b.z) + x.z, 0.f);
    r.w = fmaxf(fmaf(acc.w, inv, b.w) + x.w, 0.f);
    ((float4*)g_H)[warp * 32 + lane] = r;
}

// ---------------- layer-1 gather: out += mean(HL[nbrs]) + bl1 ---------------
// lane c holds columns 2c,2c+1 (half2 = uint), accumulate fp32
__global__ void __launch_bounds__(256)
k_gather64(const float* __restrict__ bl1, float* __restrict__ out) {
    int warp = (blockIdx.x * blockDim.x + threadIdx.x) >> 5;
    int lane = threadIdx.x & 31;
    if (warp >= N_NODES) return;
    int deg = g_cnt[warp], base = g_off[warp];
    const uint32_t* HL1 = (const uint32_t*)g_HL;   // 32 uint per row

    float2 acc = make_float2(0.f, 0.f);
    for (int i0 = 0; i0 < deg; i0 += 32) {
        int my  = (i0 + lane < deg) ? g_eidx[base + i0 + lane] : 0;
        int lim = min(32, deg - i0);
#pragma unroll 4
        for (int j = 0; j < lim; j++) {
            int s = __shfl_sync(0xffffffffu, my, j);
            uint32_t u = HL1[s * 32 + lane];
            float2 f = __half22float2(*(const __half2*)&u);
            acc.x += f.x; acc.y += f.y;
        }
    }
    float inv = 1.f / fmaxf((float)deg, 1.f);
    float2 b = ((const float2*)bl1)[lane];
    float2* out2 = (float2*)out;
    float2 o = out2[warp * 32 + lane];
    o.x += fmaf(acc.x, inv, b.x);
    o.y += fmaf(acc.y, inv, b.y);
    out2[warp * 32 + lane] = o;
}

// ---------------- launch -----------------------------------------------------
extern "C" void kernel_launch(void* const* d_in, const int* in_sizes, int n_in,
                              void* d_out, int out_size) {
    const float* x   = (const float*)d_in[0];
    const int*   ei  = (const int*)d_in[1];
    const float* Wl0 = (const float*)d_in[2];
    const float* bl0 = (const float*)d_in[3];
    const float* Wr0 = (const float*)d_in[4];
    const float* Wl1 = (const float*)d_in[5];
    const float* bl1 = (const float*)d_in[6];
    const float* Wr1 = (const float*)d_in[7];

    const int E = in_sizes[1] / 2;
    const int* src = ei;
    const int* dst = ei + E;
    const int M = N_NODES;
    const int nTiles = (M + 63) / 64;                    // 1563

    float *pXR, *pH;
    __half *pXL, *pHL;
    __nv_bfloat16 *pB0h, *pB0l, *pB1h, *pB1l;
    cudaGetSymbolAddress((void**)&pXL, g_XL);
    cudaGetSymbolAddress((void**)&pXR, g_XR);
    cudaGetSymbolAddress((void**)&pH,  g_H);
    cudaGetSymbolAddress((void**)&pHL, g_HL);
    cudaGetSymbolAddress((void**)&pB0h, g_B0h);
    cudaGetSymbolAddress((void**)&pB0l, g_B0l);
    cudaGetSymbolAddress((void**)&pB1h, g_B1h);
    cudaGetSymbolAddress((void**)&pB1l, g_B1l);

    constexpr int RB = PADK * 2;
    constexpr int SMEM0 = 2 * 64 * RB + 4 * 128 * RB;    // 174080
    constexpr int SMEM1 = 2 * 64 * RB + 4 * 64 * RB;     // 104448
    cudaFuncSetAttribute(k_mma<128>, cudaFuncAttributeMaxDynamicSharedMemorySize, SMEM0);
    cudaFuncSetAttribute(k_mma<64>,  cudaFuncAttributeMaxDynamicSharedMemorySize, SMEM1);

    // CSR build + weight conversion
    k_zero<<<(N_NODES + 255) / 256, 256>>>();
    k_count<<<(E + 255) / 256, 256>>>(dst, E);
    k_scan<<<1, 1024>>>();
    k_fill<<<(E + 255) / 256, 256>>>(src, dst, E);
    k_convW<<<192, 256>>>(Wl0, Wr0, Wl1, Wr1);

    // layer 0: persistent GEMM (XL fp16 + XR fp32), then gather+combine
    k_mma<128><<<148, 256, SMEM0>>>(x, pB0h, pB0l, pXL, pXR, M, nTiles);
    k_gather128<<<(N_NODES * 32 + 255) / 256, 256>>>(bl0);
    // layer 1: persistent GEMM (HL fp16 + root term fp32 into d_out), then gather
    k_mma<64><<<296, 256, SMEM1>>>((const float*)pH, pB1h, pB1l, pHL,
                                   (float*)d_out, M, nTiles);
    k_gather64<<<(N_NODES * 32 + 255) / 256, 256>>>(bl1, (float*)d_out);
}